// round 8
// baseline (speedup 1.0000x reference)
#include <cuda_runtime.h>
#include <cstdint>

// Sparsemax along dim=-1 for X[4096, 32000] fp32. Persistent-CTA, rotated
// solve-ahead loop + 3-buffer (64KB) TMA ring:
//  - halves H0/H1 of each row rotate through 3 smem buffers; H0(j+2) issues at
//    the TOP of iteration j (its buffer freed last iter), H1(j+2) right after
//    H0(j+1) is consumed -> the DRAM read stream always has work queued.
//  - iter j: issue H0(j+2) -> stores(j, tau known) -> wait/copy H0(j+1)
//            -> issue H1(j+2) -> wait/copy H1(j+1) -> solve tau(j+1)
//  - row in regs for t<1000 (8 x float4, v[i] = row float4 i*1000+t).
//  - tau: support subset of {x > max-1} (~31 elems), ballot compaction +
//    warp0 Newton; block-register Newton fallback. __stcs on output.

#define NTHREADS 1024
#define D        32000
#define D4       8000
#define HALF     16000         // floats per half row
#define HB       64000u        // bytes per half row
#define CSLOTS   64            // candidate slots per warp

__device__ __forceinline__ unsigned smem_u32(const void* p) {
    return (unsigned)__cvta_generic_to_shared(p);
}

__device__ __forceinline__ float warp_max_f(float v) {
    #pragma unroll
    for (int o = 16; o > 0; o >>= 1)
        v = fmaxf(v, __shfl_xor_sync(0xffffffffu, v, o));
    return v;
}

__device__ __forceinline__ void mbar_wait(unsigned mbar, unsigned ph) {
    asm volatile(
        "{\n\t"
        ".reg .pred P;\n\t"
        "WAIT_%=: \n\t"
        "mbarrier.try_wait.parity.acquire.cta.shared::cta.b64 P, [%0], %1, 0x989680;\n\t"
        "@P bra.uni DONE_%=;\n\t"
        "bra.uni WAIT_%=;\n\t"
        "DONE_%=: \n\t"
        "}\n\t" :: "r"(mbar), "r"(ph) : "memory");
}

__device__ __forceinline__ void tma_half(unsigned dst_smem, const float* src,
                                         unsigned mbar) {
    asm volatile("mbarrier.arrive.expect_tx.shared.b64 _, [%0], %1;"
                 :: "r"(mbar), "r"(HB) : "memory");
    asm volatile("cp.async.bulk.shared::cluster.global.mbarrier::complete_tx::bytes "
                 "[%0], [%1], %2, [%3];"
                 :: "r"(dst_smem), "l"(src), "r"(HB), "r"(mbar) : "memory");
}

__global__ void __launch_bounds__(NTHREADS, 1)
sparsemax_kernel(const float* __restrict__ X, float* __restrict__ Y, int nrows)
{
    __shared__ float s_warpf[32];
    __shared__ int   s_warpcnt[32];
    __shared__ float s_bcast;
    __shared__ float s_tau;
    __shared__ int   s_of;
    __shared__ __align__(8) unsigned long long s_mbar[3];

    extern __shared__ float s_dyn[];
    // 3 half-row buffers (16000 floats each), then candidate regions
    float* s_cand = s_dyn + 3 * HALF;

    const int t    = threadIdx.x;
    const int lane = t & 31;
    const int wid  = t >> 5;
    const int grid = gridDim.x;
    const float NINF = __int_as_float(0xff800000);

    if (t < 3)
        asm volatile("mbarrier.init.shared.b64 [%0], 1;"
                     :: "r"(smem_u32(&s_mbar[t])) : "memory");
    __syncthreads();

    long long row = blockIdx.x;
    if (row >= nrows) return;

    float4 v[8];
    #pragma unroll
    for (int i = 0; i < 8; i++) v[i] = make_float4(NINF, NINF, NINF, NINF);
    float vmax = NINF;
    float tau;

    // ---- prologue: load row0 via LDG (fused max); TMA row1 halves ----------
    if (t < 1000) {
        const float4* src = reinterpret_cast<const float4*>(X) + row * D4;
        #pragma unroll
        for (int i = 0; i < 8; i++) {
            v[i] = src[i * 1000 + t];
            vmax = fmaxf(vmax, fmaxf(fmaxf(v[i].x, v[i].y), fmaxf(v[i].z, v[i].w)));
        }
    }
    if (t == 0 && row + grid < nrows) {
        const float* r1 = X + (row + grid) * (long long)D;
        tma_half(smem_u32(s_dyn + 2 * HALF), r1,        smem_u32(&s_mbar[2]));  // H0(1)->buf2
        tma_half(smem_u32(s_dyn + 0 * HALF), r1 + HALF, smem_u32(&s_mbar[0]));  // H1(1)->buf0
    }
    int c0 = 2;                 // buffer holding H0 of next row
    unsigned phbits = 0;        // per-buffer phase parity (bit b)

    // =====================  solve tau for the row in regs  ==================
    #define SOLVE_TAU()                                                        \
    do {                                                                       \
        float wm = warp_max_f(vmax);                                           \
        if (lane == 0) s_warpf[wid] = wm;                                      \
        if (t == 0) s_of = 0;                                                  \
        __syncthreads();                                                       \
        const float tau0 = warp_max_f(s_warpf[lane]) - 1.0f;                   \
        {                                                                      \
            int cnt = 0;                                                       \
            const unsigned lml = (1u << lane) - 1u;                            \
            const int base = wid * CSLOTS;                                     \
            _Pragma("unroll")                                                  \
            for (int i = 0; i < 8; i++) {                                      \
                float xs[4] = {v[i].x, v[i].y, v[i].z, v[i].w};                \
                _Pragma("unroll")                                              \
                for (int c = 0; c < 4; c++) {                                  \
                    float x = xs[c];                                           \
                    bool p = x > tau0;                                         \
                    unsigned m = __ballot_sync(0xffffffffu, p);                \
                    if (p) {                                                   \
                        int pos = cnt + __popc(m & lml);                       \
                        if (pos < CSLOTS) s_cand[base + pos] = x;              \
                    }                                                          \
                    cnt += __popc(m);                                          \
                }                                                              \
            }                                                                  \
            if (lane == 0) { s_warpcnt[wid] = cnt; if (cnt > CSLOTS) s_of = 1; } \
        }                                                                      \
        __syncthreads();                                                       \
        if (wid == 0) {                                                        \
            int n = s_warpcnt[lane]; if (n > CSLOTS) n = CSLOTS;               \
            const int base = lane * CSLOTS;                                    \
            float tt = tau0;                                                   \
            for (int it = 0; it < 64; it++) {                                  \
                float s = 0.0f; int k = 0;                                     \
                for (int j2 = 0; j2 < n; j2++) {                               \
                    float c = s_cand[base + j2];                               \
                    if (c > tt) { s += c; k++; }                               \
                }                                                              \
                _Pragma("unroll")                                              \
                for (int o = 16; o > 0; o >>= 1) {                             \
                    s += __shfl_xor_sync(0xffffffffu, s, o);                   \
                    k += __shfl_xor_sync(0xffffffffu, k, o);                   \
                }                                                              \
                float nt = (s - 1.0f) / (float)k;                              \
                if (nt == tt) break;                                           \
                tt = nt;                                                       \
            }                                                                  \
            if (lane == 0) s_tau = tt;                                         \
        }                                                                      \
        __syncthreads();                                                       \
        if (s_of) {                                                            \
            float tt = tau0;                                                   \
            for (int it = 0; it < 64; it++) {                                  \
                float s = 0.0f; int k = 0;                                     \
                _Pragma("unroll")                                              \
                for (int i = 0; i < 8; i++) {                                  \
                    if (v[i].x > tt) { s += v[i].x; k++; }                     \
                    if (v[i].y > tt) { s += v[i].y; k++; }                     \
                    if (v[i].z > tt) { s += v[i].z; k++; }                     \
                    if (v[i].w > tt) { s += v[i].w; k++; }                     \
                }                                                              \
                _Pragma("unroll")                                              \
                for (int o = 16; o > 0; o >>= 1) {                             \
                    s += __shfl_xor_sync(0xffffffffu, s, o);                   \
                    k += __shfl_xor_sync(0xffffffffu, k, o);                   \
                }                                                              \
                if (lane == 0) { s_warpf[wid] = s; s_warpcnt[wid] = k; }       \
                __syncthreads();                                               \
                if (t == 0) {                                                  \
                    float S = 0.0f; int K = 0;                                 \
                    _Pragma("unroll")                                          \
                    for (int w = 0; w < 32; w++) { S += s_warpf[w]; K += s_warpcnt[w]; } \
                    s_bcast = (S - 1.0f) / (float)K;                           \
                }                                                              \
                __syncthreads();                                               \
                float nt = s_bcast;                                            \
                if (nt == tt) break;                                           \
                tt = nt;                                                       \
            }                                                                  \
            if (t == 0) s_tau = tt;                                            \
            __syncthreads();                                                   \
        }                                                                      \
        tau = s_tau;                                                           \
    } while (0)

    SOLVE_TAU();   // tau(row 0)

    for (;;) {
        const bool has1 = row + grid < nrows;
        const bool has2 = row + 2LL * grid < nrows;
        const int c1  = (c0 == 2) ? 0 : c0 + 1;
        const int bi0 = (c0 == 0) ? 2 : c0 - 1;   // target for H0(j+2)

        // ---- 1) queue H0(j+2) read immediately (buffer freed last iter) ----
        if (t == 0 && has2)
            tma_half(smem_u32(s_dyn + bi0 * HALF),
                     X + (row + 2LL * grid) * (long long)D, smem_u32(&s_mbar[bi0]));

        // ---- 2) stores for current row (tau precomputed) --------------------
        if (t < 1000) {
            float4* dst = reinterpret_cast<float4*>(Y) + row * D4;
            #pragma unroll
            for (int i = 0; i < 8; i++) {
                float4 o;
                o.x = fmaxf(v[i].x - tau, 0.0f);
                o.y = fmaxf(v[i].y - tau, 0.0f);
                o.z = fmaxf(v[i].z - tau, 0.0f);
                o.w = fmaxf(v[i].w - tau, 0.0f);
                __stcs(dst + i * 1000 + t, o);
            }
        }

        if (!has1) break;

        // ---- 3) consume H0(j+1) ---------------------------------------------
        mbar_wait(smem_u32(&s_mbar[c0]), (phbits >> c0) & 1u);
        phbits ^= 1u << c0;
        vmax = NINF;
        if (t < 1000) {
            const float4* b4 = reinterpret_cast<const float4*>(s_dyn + c0 * HALF);
            #pragma unroll
            for (int i = 0; i < 4; i++) {
                float4 x = b4[i * 1000 + t];
                v[i] = x;
                vmax = fmaxf(vmax, fmaxf(fmaxf(x.x, x.y), fmaxf(x.z, x.w)));
            }
        }
        __syncthreads();                     // buf c0 consumed

        // ---- 4) queue H1(j+2) into the buffer just freed --------------------
        if (t == 0 && has2)
            tma_half(smem_u32(s_dyn + c0 * HALF),
                     X + (row + 2LL * grid) * (long long)D + HALF,
                     smem_u32(&s_mbar[c0]));

        // ---- 5) consume H1(j+1) ---------------------------------------------
        mbar_wait(smem_u32(&s_mbar[c1]), (phbits >> c1) & 1u);
        phbits ^= 1u << c1;
        if (t < 1000) {
            const float4* b4 = reinterpret_cast<const float4*>(s_dyn + c1 * HALF);
            #pragma unroll
            for (int i = 0; i < 4; i++) {
                float4 x = b4[i * 1000 + t];
                v[4 + i] = x;
                vmax = fmaxf(vmax, fmaxf(fmaxf(x.x, x.y), fmaxf(x.z, x.w)));
            }
        }
        __syncthreads();                     // buf c1 consumed

        // ---- 6) advance, solve tau for the new row ---------------------------
        row += grid;
        c0 = bi0;
        SOLVE_TAU();
    }
}

extern "C" void kernel_launch(void* const* d_in, const int* in_sizes, int n_in,
                              void* d_out, int out_size)
{
    const float* X = (const float*)d_in[0];
    float* Y = (float*)d_out;
    int rows = in_sizes[0] / D;                 // 4096

    int sms = 148;
    cudaDeviceGetAttribute(&sms, cudaDevAttrMultiProcessorCount, 0);
    int grid = (rows < sms) ? rows : sms;       // persistent: one CTA per SM

    size_t dyn = (size_t)(3 * HALF + 32 * CSLOTS) * sizeof(float);  // 200192 B
    cudaFuncSetAttribute(sparsemax_kernel,
                         cudaFuncAttributeMaxDynamicSharedMemorySize, (int)dyn);
    sparsemax_kernel<<<grid, NTHREADS, dyn>>>(X, Y, rows);
}